// round 16
// baseline (speedup 1.0000x reference)
#include <cuda_runtime.h>

// RotationPerturbationLayer as zero-padded bilinear rotation resample.
// theta: [B=4] deg, image: [C=3, H=80, W=80] fp32 -> out [B, C, H, W].
//
// R14: channel-split parallelism. One thread per (b, ch, y, x) = 76800
// threads, 240 blocks x 320 -> all 148 SMs active (~16 warps/SM), and the
// per-thread tail after the gather wait shrinks to 4 FMA + 1 store.
// Keeps proven body: theta load first, truncation-floor, bool-AND masks.

#define H 80
#define W 80
#define C 3
#define B 4
#define NPIX (H * W)

__global__ __launch_bounds__(320)
void rot_bilinear_kernel(const float* __restrict__ theta,
                         const float* __restrict__ image,
                         float* __restrict__ out) {
    const int b  = blockIdx.y;                       // 0..3
    // issue the broadcast load immediately; latency overlaps setup below
    float thdeg = __ldg(theta + b);

    const int x  = threadIdx.x;                      // 0..79
    const int y  = blockIdx.x * 4 + threadIdx.y;     // 0..79
    const int ch = blockIdx.z;                       // 0..2

    const float cx = (W - 1) * 0.5f;   // 39.5
    const float cy = (H - 1) * 0.5f;

    float x_rel = (float)x - cx;
    float y_rel = (float)y - cy;

    float th = thdeg * 0.017453292519943295f;
    float s, c;
    __sincosf(th, &s, &c);

    // rotation matrix [[cos, sin], [-sin, cos]]
    float src_x = fmaf(c,  x_rel, fmaf(s, y_rel, cx));
    float src_y = fmaf(-s, x_rel, fmaf(c, y_rel, cy));

    // truncation-floor: src_* >= -56.1, so +64 keeps it positive;
    // (int) truncation == floor for non-negative values. Exact in fp32.
    int x0 = (int)(src_x + 64.0f) - 64;
    int y0 = (int)(src_y + 64.0f) - 64;
    int x1 = x0 + 1;
    int y1 = y0 + 1;
    float ax = src_x - (float)x0;
    float ay = src_y - (float)y0;

    // tent weights + bool-AND zero-pad masks (best-measured formulation)
    float w00 = (1.0f - ax) * (1.0f - ay);
    float w10 = ax * (1.0f - ay);
    float w01 = (1.0f - ax) * ay;
    float w11 = ax * ay;

    bool x0ok = (x0 >= 0) & (x0 < W);
    bool x1ok = (x1 >= 0) & (x1 < W);
    bool y0ok = (y0 >= 0) & (y0 < H);
    bool y1ok = (y1 >= 0) & (y1 < H);

    float m00 = (x0ok & y0ok) ? w00 : 0.0f;
    float m10 = (x1ok & y0ok) ? w10 : 0.0f;
    float m01 = (x0ok & y1ok) ? w01 : 0.0f;
    float m11 = (x1ok & y1ok) ? w11 : 0.0f;

    // clamp indices so addresses are valid (weight already zeroed)
    int xc0 = min(max(x0, 0), W - 1);
    int xc1 = min(max(x1, 0), W - 1);
    int yc0 = min(max(y0, 0), H - 1);
    int yc1 = min(max(y1, 0), H - 1);

    const float* ic = image + ch * NPIX;
    int i00 = yc0 * W + xc0;
    int i10 = yc0 * W + xc1;
    int i01 = yc1 * W + xc0;
    int i11 = yc1 * W + xc1;

    // 4 independent gathers, batched
    float v00 = __ldg(ic + i00);
    float v10 = __ldg(ic + i10);
    float v01 = __ldg(ic + i01);
    float v11 = __ldg(ic + i11);

    float r = m00 * v00;
    r = fmaf(m10, v10, r);
    r = fmaf(m01, v01, r);
    r = fmaf(m11, v11, r);

    out[((size_t)b * C + ch) * NPIX + y * W + x] = r;
}

extern "C" void kernel_launch(void* const* d_in, const int* in_sizes, int n_in,
                              void* d_out, int out_size) {
    const float* theta = (const float*)d_in[0];
    const float* image = (const float*)d_in[1];
    if (n_in >= 2 && in_sizes[0] != 4 && in_sizes[1] == 4) {
        theta = (const float*)d_in[1];
        image = (const float*)d_in[0];
    }
    float* out = (float*)d_out;

    dim3 block(80, 4, 1);          // 320 threads
    dim3 grid(H / 4, B, C);        // 20 x 4 x 3 = 240 blocks, one wave on 148 SMs
    rot_bilinear_kernel<<<grid, block>>>(theta, image, out);
}

// round 17
// speedup vs baseline: 1.1250x; 1.1250x over previous
#include <cuda_runtime.h>

// RotationPerturbationLayer as zero-padded bilinear rotation resample.
// theta: [B=4] deg, image: [C=3, H=80, W=80] fp32 -> out [B, C, H, W].
//
// R17 = R13 verbatim restore (best measured e2e: 6.21us).
// Series evidence: e2e is pinned at a ~6.2-6.9us graph-replay+launch floor;
// kernel-dur 4.4-5.1us across all geometries (80x320 1px, 240-block
// channel-split, 2px/thread) with no e2e correlation. R13's config is the
// best-measured point; protect it.
//   - 80 blocks x 320 threads, 1 px/thread (25600 threads, 10 warps/SM)
//   - theta load issued first (L2 latency overlaps index setup)
//   - truncation-floor (+64 bias, exact for this coordinate range)
//   - bool-AND zero-pad masks (best codegen of the three mask forms tried)
//   - 12 batched gathers -> one exposed L2 latency per warp

#define H 80
#define W 80
#define C 3
#define B 4
#define NPIX (H * W)

__global__ __launch_bounds__(320)
void rot_bilinear_kernel(const float* __restrict__ theta,
                         const float* __restrict__ image,
                         float* __restrict__ out) {
    const int b = blockIdx.y;                        // 0..3
    // issue the broadcast load immediately; latency overlaps setup below
    float thdeg = __ldg(theta + b);

    const int x = threadIdx.x;                       // 0..79
    const int y = blockIdx.x * 4 + threadIdx.y;      // 0..79

    const float cx = (W - 1) * 0.5f;   // 39.5
    const float cy = (H - 1) * 0.5f;

    float x_rel = (float)x - cx;
    float y_rel = (float)y - cy;

    float th = thdeg * 0.017453292519943295f;
    float s, c;
    __sincosf(th, &s, &c);

    // rotation matrix [[cos, sin], [-sin, cos]]
    float src_x = fmaf(c,  x_rel, fmaf(s, y_rel, cx));
    float src_y = fmaf(-s, x_rel, fmaf(c, y_rel, cy));

    // truncation-floor: src_* in [-56.1, 95.6+], so +64 keeps it positive;
    // (int) truncation == floor for non-negative values. x0 exact in fp32.
    int x0 = (int)(src_x + 64.0f) - 64;
    int y0 = (int)(src_y + 64.0f) - 64;
    int x1 = x0 + 1;
    int y1 = y0 + 1;
    float ax = src_x - (float)x0;
    float ay = src_y - (float)y0;

    // tent weights (full weights, bool-AND zero-pad masks)
    float w00 = (1.0f - ax) * (1.0f - ay);
    float w10 = ax * (1.0f - ay);
    float w01 = (1.0f - ax) * ay;
    float w11 = ax * ay;

    bool x0ok = (x0 >= 0) & (x0 < W);
    bool x1ok = (x1 >= 0) & (x1 < W);
    bool y0ok = (y0 >= 0) & (y0 < H);
    bool y1ok = (y1 >= 0) & (y1 < H);

    float m00 = (x0ok & y0ok) ? w00 : 0.0f;
    float m10 = (x1ok & y0ok) ? w10 : 0.0f;
    float m01 = (x0ok & y1ok) ? w01 : 0.0f;
    float m11 = (x1ok & y1ok) ? w11 : 0.0f;

    // clamp indices so addresses are valid (weight already zeroed)
    int xc0 = min(max(x0, 0), W - 1);
    int xc1 = min(max(x1, 0), W - 1);
    int yc0 = min(max(y0, 0), H - 1);
    int yc1 = min(max(y1, 0), H - 1);

    int i00 = yc0 * W + xc0;
    int i10 = yc0 * W + xc1;
    int i01 = yc1 * W + xc0;
    int i11 = yc1 * W + xc1;

    const float* c0 = image;
    const float* c1 = image + NPIX;
    const float* c2 = image + 2 * NPIX;

    // 12 independent gathers, batched: one exposed L2 latency per warp
    float v00_0 = __ldg(c0 + i00);
    float v10_0 = __ldg(c0 + i10);
    float v01_0 = __ldg(c0 + i01);
    float v11_0 = __ldg(c0 + i11);
    float v00_1 = __ldg(c1 + i00);
    float v10_1 = __ldg(c1 + i10);
    float v01_1 = __ldg(c1 + i01);
    float v11_1 = __ldg(c1 + i11);
    float v00_2 = __ldg(c2 + i00);
    float v10_2 = __ldg(c2 + i10);
    float v01_2 = __ldg(c2 + i01);
    float v11_2 = __ldg(c2 + i11);

    int pix = y * W + x;
    float* ob = out + (size_t)b * C * NPIX + pix;

    float r0 = m00 * v00_0;
    r0 = fmaf(m10, v10_0, r0);
    r0 = fmaf(m01, v01_0, r0);
    r0 = fmaf(m11, v11_0, r0);

    float r1 = m00 * v00_1;
    r1 = fmaf(m10, v10_1, r1);
    r1 = fmaf(m01, v01_1, r1);
    r1 = fmaf(m11, v11_1, r1);

    float r2 = m00 * v00_2;
    r2 = fmaf(m10, v10_2, r2);
    r2 = fmaf(m01, v01_2, r2);
    r2 = fmaf(m11, v11_2, r2);

    ob[0 * NPIX] = r0;
    ob[1 * NPIX] = r1;
    ob[2 * NPIX] = r2;
}

extern "C" void kernel_launch(void* const* d_in, const int* in_sizes, int n_in,
                              void* d_out, int out_size) {
    const float* theta = (const float*)d_in[0];
    const float* image = (const float*)d_in[1];
    if (n_in >= 2 && in_sizes[0] != 4 && in_sizes[1] == 4) {
        theta = (const float*)d_in[1];
        image = (const float*)d_in[0];
    }
    float* out = (float*)d_out;

    dim3 block(80, 4, 1);        // 320 threads, 1 px/thread
    dim3 grid(H / 4, B, 1);      // 20 x 4 = 80 blocks, exactly one wave
    rot_bilinear_kernel<<<grid, block>>>(theta, image, out);
}